// round 11
// baseline (speedup 1.0000x reference)
#include <cuda_runtime.h>

#define REPS 1e-4f
#define GBX  8                    // column groups (512 cols each)
#define GBY  111                  // row bands (36-37 rows each)
#define NBLK_PROJ (GBX * GBY)     // 888 blocks = 148 SMs * 6

// Scratch (no allocations allowed). Zero-init at load; last k_proj block
// resets g_M/g_cnt after consuming, so graph replays see clean state.
__device__ float    g_M[25 * 32];  // each accumulator on its own 128B line
__device__ unsigned g_cnt;
__device__ float    g_H[5 * 2048]; // H = A5 @ W2, produced by last proj block

// ---- packed f32x2 helpers (k_out only) -------------------------------------
__device__ __forceinline__ unsigned long long ffma2(unsigned long long a,
                                                    unsigned long long b,
                                                    unsigned long long c) {
    unsigned long long d;
    asm("fma.rn.f32x2 %0, %1, %2, %3;" : "=l"(d) : "l"(a), "l"(b), "l"(c));
    return d;
}
__device__ __forceinline__ float2 unpack2(unsigned long long v) {
    float2 r;
    asm("mov.b64 {%0, %1}, %2;" : "=f"(r.x), "=f"(r.y) : "l"(v));
    return r;
}
__device__ __forceinline__ unsigned long long pack_dup(float v) {
    unsigned long long d;
    asm("mov.b64 %0, {%1, %1};" : "=l"(d) : "f"(v));
    return d;
}

// ---------------------------------------------------------------------------
// K1: t[j][a] = sum_i W1[i,a]*X[i,j]; fold M[a][b] += t[j][a]*W1[j,b] once.
// OCCUPANCY EXPERIMENT: 2 cols/thread (tacc=10 regs, ~33 live, no spill at
// the 40-reg cap) -> __launch_bounds__(256,6) = 48 warps/SM, grid (8,111) =
// 888 blocks = exactly one wave. Same banded structure + 4-row load batching
// as the best-measured R4 body; plain FFMA.
// Last block: thread 0 runs 5x5 Jacobi; 256 threads emit H = A5@W2.
// ---------------------------------------------------------------------------
__global__ __launch_bounds__(256, 6) void k_proj(const float* __restrict__ X,
                                                 const float* __restrict__ W1,
                                                 const float* __restrict__ W2) {
    const int tid = threadIdx.x;
    const int j0  = blockIdx.x * 512 + tid * 2;
    const int r0  = (blockIdx.y * 4096) / GBY;
    const int r1  = ((blockIdx.y + 1) * 4096) / GBY;
    const int R   = r1 - r0;                      // 36 or 37

    __shared__ float sW1[37 * 5];
    __shared__ float sM[8][25];
    __shared__ float sA5[25];
    __shared__ bool  sLast;
    if (tid < R * 5) sW1[tid] = W1[r0 * 5 + tid];
    __syncthreads();

    float tacc[2][5];                             // 10 accumulator regs
#pragma unroll
    for (int cc = 0; cc < 2; cc++)
#pragma unroll
        for (int a = 0; a < 5; a++) tacc[cc][a] = 0.f;

    const float* Xb = X + (size_t)r0 * 4096 + j0;
    int r = 0;
    for (; r + 4 <= R; r += 4) {
        const float2 x0 = *reinterpret_cast<const float2*>(Xb + (size_t)(r + 0) * 4096);
        const float2 x1 = *reinterpret_cast<const float2*>(Xb + (size_t)(r + 1) * 4096);
        const float2 x2 = *reinterpret_cast<const float2*>(Xb + (size_t)(r + 2) * 4096);
        const float2 x3 = *reinterpret_cast<const float2*>(Xb + (size_t)(r + 3) * 4096);
        const float2 xs[4] = {x0, x1, x2, x3};
#pragma unroll
        for (int k = 0; k < 4; k++) {
            float w[5];
#pragma unroll
            for (int a = 0; a < 5; a++) w[a] = sW1[(r + k) * 5 + a];
#pragma unroll
            for (int a = 0; a < 5; a++) {
                tacc[0][a] += xs[k].x * w[a];
                tacc[1][a] += xs[k].y * w[a];
            }
        }
    }
    for (; r < R; r++) {
        const float2 x = *reinterpret_cast<const float2*>(Xb + (size_t)r * 4096);
        float w[5];
#pragma unroll
        for (int a = 0; a < 5; a++) w[a] = sW1[r * 5 + a];
#pragma unroll
        for (int a = 0; a < 5; a++) {
            tacc[0][a] += x.x * w[a];
            tacc[1][a] += x.y * w[a];
        }
    }

    // Fold with W1[j,b]: 2 columns, once per thread
    float mp[5][5];
#pragma unroll
    for (int a = 0; a < 5; a++)
#pragma unroll
        for (int b = 0; b < 5; b++) mp[a][b] = 0.f;
#pragma unroll
    for (int cc = 0; cc < 2; cc++) {
        float w1j[5];
#pragma unroll
        for (int b = 0; b < 5; b++) w1j[b] = __ldg(W1 + (j0 + cc) * 5 + b);
#pragma unroll
        for (int a = 0; a < 5; a++)
#pragma unroll
            for (int b = 0; b < 5; b++) mp[a][b] += tacc[cc][a] * w1j[b];
    }

    // Block reduce 25 values -> 25 padded global atomics
    const int lane = tid & 31, warp = tid >> 5;
#pragma unroll
    for (int e = 0; e < 25; e++) {
        float v = mp[e / 5][e % 5];
#pragma unroll
        for (int o = 16; o > 0; o >>= 1) v += __shfl_down_sync(0xffffffffu, v, o);
        if (lane == 0) sM[warp][e] = v;
    }
    __syncthreads();
    if (tid < 25) {
        float v = 0.f;
#pragma unroll
        for (int wq = 0; wq < 8; wq++) v += sM[wq][tid];
        atomicAdd(&g_M[tid * 32], v);
    }
    if (tid == 0) {
        __threadfence();
        sLast = (atomicAdd(&g_cnt, 1u) == (unsigned)NBLK_PROJ - 1u);
    }
    __syncthreads();
    if (!sLast) return;

    // ---- Last block. Thread 0: B = M*M^T ; Jacobi ; A5 -> shared ----
    if (tid == 0) {
        float m[5][5], b[5][5], u[5][5];
#pragma unroll
        for (int a = 0; a < 5; a++)
#pragma unroll
            for (int c = 0; c < 5; c++) m[a][c] = __ldcg(&g_M[(a * 5 + c) * 32]);

        float tr = 0.f;
#pragma unroll
        for (int a = 0; a < 5; a++)
#pragma unroll
            for (int c = 0; c < 5; c++) {
                float s = 0.f;
#pragma unroll
                for (int k = 0; k < 5; k++) s += m[a][k] * m[c][k];
                b[a][c] = s;
                u[a][c] = (a == c) ? 1.f : 0.f;
                if (a == c) tr += s;
            }
        const float skip_tol = 1e-7f * tr;

#pragma unroll
        for (int sweep = 0; sweep < 5; sweep++) {
#pragma unroll
            for (int p = 0; p < 4; p++) {
#pragma unroll
                for (int q = p + 1; q < 5; q++) {
                    const float apq = b[p][q];
                    if (fabsf(apq) > skip_tol) {
                        const float tau = (b[q][q] - b[p][p]) / (2.f * apq);
                        const float t   = copysignf(1.f, tau) / (fabsf(tau) + sqrtf(1.f + tau * tau));
                        const float c   = rsqrtf(1.f + t * t);
                        const float s   = t * c;
#pragma unroll
                        for (int k = 0; k < 5; k++) {
                            const float bkp = b[k][p], bkq = b[k][q];
                            b[k][p] = c * bkp - s * bkq;
                            b[k][q] = s * bkp + c * bkq;
                        }
#pragma unroll
                        for (int k = 0; k < 5; k++) {
                            const float bpk = b[p][k], bqk = b[q][k];
                            b[p][k] = c * bpk - s * bqk;
                            b[q][k] = s * bpk + c * bqk;
                            const float ukp = u[k][p], ukq = u[k][q];
                            u[k][p] = c * ukp - s * ukq;
                            u[k][q] = s * ukp + c * ukq;
                        }
                    }
                }
            }
        }

        float f[5];
#pragma unroll
        for (int d = 0; d < 5; d++) {
            const float lam = fmaxf(b[d][d], 0.f);
            f[d] = fmaxf(sqrtf(lam), REPS) - REPS;
        }
#pragma unroll
        for (int a = 0; a < 5; a++)
#pragma unroll
            for (int c = 0; c < 5; c++) {
                float s = 0.f;
#pragma unroll
                for (int d = 0; d < 5; d++) s += u[a][d] * f[d] * u[c][d];
                sA5[a * 5 + c] = s;
            }

        // Reset scratch for the next graph replay
#pragma unroll
        for (int e = 0; e < 25; e++) g_M[e * 32] = 0.f;
        g_cnt = 0u;
    }
    __syncthreads();

    // ---- All 256 threads: H[a][j] = sum_b A5[a][b] * W2[b][j] -> g_H ----
    float a5[5][5];
#pragma unroll
    for (int a = 0; a < 5; a++)
#pragma unroll
        for (int c = 0; c < 5; c++) a5[a][c] = sA5[a * 5 + c];
#pragma unroll
    for (int k = 0; k < 8; k++) {
        const int j = tid + 256 * k;
        float w2j[5];
#pragma unroll
        for (int b2 = 0; b2 < 5; b2++) w2j[b2] = __ldg(W2 + b2 * 2048 + j);
#pragma unroll
        for (int a = 0; a < 5; a++) {
            float s = 0.f;
#pragma unroll
            for (int b2 = 0; b2 < 5; b2++) s += a5[a][b2] * w2j[b2];
            g_H[a * 2048 + j] = s;
        }
    }
}

// ---------------------------------------------------------------------------
// K2 (R10 variant — best measured, 6.7us): z = W2^T H + EPS*I.
// W2 band slice staged in smem as duplicated pairs ONCE; inner row loop is
// 5 LDS.64 + 10 fma.rn.f32x2 + STG.128 — zero LDG.
// ---------------------------------------------------------------------------
__global__ __launch_bounds__(256, 4) void k_out(const float* __restrict__ W2,
                                                float* __restrict__ out) {
    const int tid = threadIdx.x;
    const int jo  = blockIdx.x * 1024 + tid * 4;
    const int o0  = (blockIdx.y * 2048) / 296;
    const int o1  = ((blockIdx.y + 1) * 2048) / 296;
    const int RR  = o1 - o0;                      // 6 or 7

    __shared__ __align__(8) unsigned long long sW2d[8 * 5];  // (w,w) per row,a
    if (tid < RR * 5) {
        const int rr = tid / 5, a = tid % 5;
        sW2d[tid] = pack_dup(__ldg(W2 + a * 2048 + o0 + rr));
    }

    ulonglong2 h[5];
#pragma unroll
    for (int a = 0; a < 5; a++)
        h[a] = *reinterpret_cast<const ulonglong2*>(g_H + a * 2048 + jo);
    __syncthreads();

    for (int rr = 0; rr < RR; rr++) {
        const int i = o0 + rr;
        unsigned long long wd[5];
#pragma unroll
        for (int a = 0; a < 5; a++) wd[a] = sW2d[rr * 5 + a];

        unsigned long long vlo = 0ull, vhi = 0ull;
#pragma unroll
        for (int a = 0; a < 5; a++) {
            vlo = ffma2(wd[a], h[a].x, vlo);
            vhi = ffma2(wd[a], h[a].y, vhi);
        }
        const float2 flo = unpack2(vlo);
        const float2 fhi = unpack2(vhi);
        float4 v;
        v.x = flo.x; v.y = flo.y; v.z = fhi.x; v.w = fhi.y;

        const int d = i - jo;
        if ((unsigned)d < 4u) {
            if (d == 0) v.x += REPS;
            else if (d == 1) v.y += REPS;
            else if (d == 2) v.z += REPS;
            else v.w += REPS;
        }
        *reinterpret_cast<float4*>(out + (size_t)i * 2048 + jo) = v;
    }
}

// ---------------------------------------------------------------------------
extern "C" void kernel_launch(void* const* d_in, const int* in_sizes, int n_in,
                              void* d_out, int out_size) {
    const float* X  = (const float*)d_in[0];   // (1, 4096, 4096) f32
    const float* W1 = (const float*)d_in[1];   // (4096, 5) f32
    const float* W2 = (const float*)d_in[2];   // (5, 2048) f32
    float* out = (float*)d_out;                // (2048, 2048) f32

    k_proj<<<dim3(GBX, GBY), 256>>>(X, W1, W2);
    k_out <<<dim3(2, 296), 256>>>(W2, out);
}

// round 12
// speedup vs baseline: 1.2245x; 1.2245x over previous
#include <cuda_runtime.h>

#define REPS 1e-4f
#define GYP 148
#define NBLK_PROJ (4 * GYP)

// Scratch (no allocations allowed). Zero-init at load; last k_proj block
// resets g_M/g_cnt after consuming, so graph replays see clean state.
__device__ float    g_M[25 * 32];  // each accumulator on its own 128B line
__device__ unsigned g_cnt;
__device__ float    g_H[5 * 2048]; // H = A5 @ W2, produced by last proj block

// ---- packed f32x2 helpers (k_out only) -------------------------------------
__device__ __forceinline__ unsigned long long ffma2(unsigned long long a,
                                                    unsigned long long b,
                                                    unsigned long long c) {
    unsigned long long d;
    asm("fma.rn.f32x2 %0, %1, %2, %3;" : "=l"(d) : "l"(a), "l"(b), "l"(c));
    return d;
}
__device__ __forceinline__ float2 unpack2(unsigned long long v) {
    float2 r;
    asm("mov.b64 {%0, %1}, %2;" : "=f"(r.x), "=f"(r.y) : "l"(v));
    return r;
}
__device__ __forceinline__ unsigned long long pack_dup(float v) {
    unsigned long long d;
    asm("mov.b64 %0, {%1, %1};" : "=l"(d) : "f"(v));
    return d;
}
// fast sqrt for x >= 1 (x * rsqrt(x)); short MUFU chain instead of IEEE seq
__device__ __forceinline__ float fsqrt_fast(float x) {
    return x * __frsqrt_rn(x);
}

// ---------------------------------------------------------------------------
// K1 (R4 body — best measured): t[j][a] = sum_i W1[i,a]*X[i,j]; fold
// M[a][b] += t[j][a]*W1[j,b] once. Block: 256 thr, 1024-col tile, contiguous
// row band, W1 staged in smem, 4-row load batching. 4 blocks/SM.
// Last block: thread 0 runs FAST-MATH 5x5 Jacobi (short MUFU chains — the
// tail is whole-GPU-serial, so chain latency is all that matters), then 256
// threads emit H = A5@W2.
// ---------------------------------------------------------------------------
__global__ __launch_bounds__(256, 4) void k_proj(const float* __restrict__ X,
                                                 const float* __restrict__ W1,
                                                 const float* __restrict__ W2) {
    const int tid = threadIdx.x;
    const int j0  = blockIdx.x * 1024 + tid * 4;
    const int r0  = (blockIdx.y * 4096) / GYP;
    const int r1  = ((blockIdx.y + 1) * 4096) / GYP;
    const int R   = r1 - r0;                      // 27 or 28

    __shared__ float sW1[28 * 5];
    __shared__ float sM[8][25];
    __shared__ float sA5[25];
    __shared__ bool  sLast;
    if (tid < R * 5) sW1[tid] = W1[r0 * 5 + tid];
    __syncthreads();

    float tacc[4][5];
#pragma unroll
    for (int cc = 0; cc < 4; cc++)
#pragma unroll
        for (int a = 0; a < 5; a++) tacc[cc][a] = 0.f;

    const float* Xb = X + (size_t)r0 * 4096 + j0;
    int r = 0;
    for (; r + 4 <= R; r += 4) {
        const float4 x0 = *reinterpret_cast<const float4*>(Xb + (size_t)(r + 0) * 4096);
        const float4 x1 = *reinterpret_cast<const float4*>(Xb + (size_t)(r + 1) * 4096);
        const float4 x2 = *reinterpret_cast<const float4*>(Xb + (size_t)(r + 2) * 4096);
        const float4 x3 = *reinterpret_cast<const float4*>(Xb + (size_t)(r + 3) * 4096);
        const float4 xs[4] = {x0, x1, x2, x3};
#pragma unroll
        for (int k = 0; k < 4; k++) {
            const float xv[4] = {xs[k].x, xs[k].y, xs[k].z, xs[k].w};
            float w[5];
#pragma unroll
            for (int a = 0; a < 5; a++) w[a] = sW1[(r + k) * 5 + a];
#pragma unroll
            for (int cc = 0; cc < 4; cc++)
#pragma unroll
                for (int a = 0; a < 5; a++) tacc[cc][a] += xv[cc] * w[a];
        }
    }
    for (; r < R; r++) {
        const float4 x = *reinterpret_cast<const float4*>(Xb + (size_t)r * 4096);
        const float xv[4] = {x.x, x.y, x.z, x.w};
        float w[5];
#pragma unroll
        for (int a = 0; a < 5; a++) w[a] = sW1[r * 5 + a];
#pragma unroll
        for (int cc = 0; cc < 4; cc++)
#pragma unroll
            for (int a = 0; a < 5; a++) tacc[cc][a] += xv[cc] * w[a];
    }

    // Fold with W1[j,b] once per thread
    float mp[5][5];
#pragma unroll
    for (int a = 0; a < 5; a++)
#pragma unroll
        for (int b = 0; b < 5; b++) mp[a][b] = 0.f;
#pragma unroll
    for (int cc = 0; cc < 4; cc++) {
        float w1j[5];
#pragma unroll
        for (int b = 0; b < 5; b++) w1j[b] = __ldg(W1 + (j0 + cc) * 5 + b);
#pragma unroll
        for (int a = 0; a < 5; a++)
#pragma unroll
            for (int b = 0; b < 5; b++) mp[a][b] += tacc[cc][a] * w1j[b];
    }

    // Block reduce 25 values -> 25 padded global atomics
    const int lane = tid & 31, warp = tid >> 5;
#pragma unroll
    for (int e = 0; e < 25; e++) {
        float v = mp[e / 5][e % 5];
#pragma unroll
        for (int o = 16; o > 0; o >>= 1) v += __shfl_down_sync(0xffffffffu, v, o);
        if (lane == 0) sM[warp][e] = v;
    }
    __syncthreads();
    if (tid < 25) {
        float v = 0.f;
#pragma unroll
        for (int wq = 0; wq < 8; wq++) v += sM[wq][tid];
        atomicAdd(&g_M[tid * 32], v);
    }
    if (tid == 0) {
        __threadfence();
        sLast = (atomicAdd(&g_cnt, 1u) == (unsigned)NBLK_PROJ - 1u);
    }
    __syncthreads();
    if (!sLast) return;

    // ---- Last block. Thread 0: B = M*M^T ; FAST Jacobi ; A5 -> shared ----
    if (tid == 0) {
        float m[5][5], b[5][5], u[5][5];
#pragma unroll
        for (int a = 0; a < 5; a++)
#pragma unroll
            for (int c = 0; c < 5; c++) m[a][c] = __ldcg(&g_M[(a * 5 + c) * 32]);

        float tr = 0.f;
#pragma unroll
        for (int a = 0; a < 5; a++)
#pragma unroll
            for (int c = 0; c < 5; c++) {
                float s = 0.f;
#pragma unroll
                for (int k = 0; k < 5; k++) s += m[a][k] * m[c][k];
                b[a][c] = s;
                u[a][c] = (a == c) ? 1.f : 0.f;
                if (a == c) tr += s;
            }
        const float skip_tol = 1e-7f * tr;

#pragma unroll
        for (int sweep = 0; sweep < 5; sweep++) {
#pragma unroll
            for (int p = 0; p < 4; p++) {
#pragma unroll
                for (int q = p + 1; q < 5; q++) {
                    const float apq = b[p][q];
                    if (fabsf(apq) > skip_tol) {
                        // fast-math chain: __fdividef + rsqrt-sqrt (short
                        // MUFU sequences; 500x rel_err headroom available)
                        const float tau = __fdividef(b[q][q] - b[p][p], 2.f * apq);
                        const float h   = fsqrt_fast(1.f + tau * tau);
                        const float t   = copysignf(__fdividef(1.f, fabsf(tau) + h), tau);
                        const float c   = __frsqrt_rn(1.f + t * t);
                        const float s   = t * c;
#pragma unroll
                        for (int k = 0; k < 5; k++) {
                            const float bkp = b[k][p], bkq = b[k][q];
                            b[k][p] = c * bkp - s * bkq;
                            b[k][q] = s * bkp + c * bkq;
                        }
#pragma unroll
                        for (int k = 0; k < 5; k++) {
                            const float bpk = b[p][k], bqk = b[q][k];
                            b[p][k] = c * bpk - s * bqk;
                            b[q][k] = s * bpk + c * bqk;
                            const float ukp = u[k][p], ukq = u[k][q];
                            u[k][p] = c * ukp - s * ukq;
                            u[k][q] = s * ukp + c * ukq;
                        }
                    }
                }
            }
        }

        float f[5];
#pragma unroll
        for (int d = 0; d < 5; d++) {
            const float lam = fmaxf(b[d][d], 0.f);
            f[d] = fmaxf(sqrtf(lam), REPS) - REPS;
        }
#pragma unroll
        for (int a = 0; a < 5; a++)
#pragma unroll
            for (int c = 0; c < 5; c++) {
                float s = 0.f;
#pragma unroll
                for (int d = 0; d < 5; d++) s += u[a][d] * f[d] * u[c][d];
                sA5[a * 5 + c] = s;
            }

        // Reset scratch for the next graph replay
#pragma unroll
        for (int e = 0; e < 25; e++) g_M[e * 32] = 0.f;
        g_cnt = 0u;
    }
    __syncthreads();

    // ---- All 256 threads: H[a][j] = sum_b A5[a][b] * W2[b][j] -> g_H ----
    float a5[5][5];
#pragma unroll
    for (int a = 0; a < 5; a++)
#pragma unroll
        for (int c = 0; c < 5; c++) a5[a][c] = sA5[a * 5 + c];
#pragma unroll
    for (int k = 0; k < 8; k++) {
        const int j = tid + 256 * k;
        float w2j[5];
#pragma unroll
        for (int b2 = 0; b2 < 5; b2++) w2j[b2] = __ldg(W2 + b2 * 2048 + j);
#pragma unroll
        for (int a = 0; a < 5; a++) {
            float s = 0.f;
#pragma unroll
            for (int b2 = 0; b2 < 5; b2++) s += a5[a][b2] * w2j[b2];
            g_H[a * 2048 + j] = s;
        }
    }
}

// ---------------------------------------------------------------------------
// K2 (R10 body + PDL): launched with ProgrammaticStreamSerialization so its
// blocks become resident and run the W2/smem prologue WHILE k_proj's last
// block is still doing Jacobi+H; griddepcontrol.wait gates the g_H read.
// ---------------------------------------------------------------------------
__global__ __launch_bounds__(256, 4) void k_out(const float* __restrict__ W2,
                                                float* __restrict__ out) {
    const int tid = threadIdx.x;
    const int jo  = blockIdx.x * 1024 + tid * 4;
    const int o0  = (blockIdx.y * 2048) / 296;
    const int o1  = ((blockIdx.y + 1) * 2048) / 296;
    const int RR  = o1 - o0;                      // 6 or 7

    __shared__ __align__(8) unsigned long long sW2d[8 * 5];  // (w,w) per row,a
    if (tid < RR * 5) {
        const int rr = tid / 5, a = tid % 5;
        sW2d[tid] = pack_dup(__ldg(W2 + a * 2048 + o0 + rr));
    }

    // Wait for k_proj completion (g_H ready) — prologue above already done.
    asm volatile("griddepcontrol.wait;" ::: "memory");

    ulonglong2 h[5];
#pragma unroll
    for (int a = 0; a < 5; a++)
        h[a] = *reinterpret_cast<const ulonglong2*>(g_H + a * 2048 + jo);
    __syncthreads();

    for (int rr = 0; rr < RR; rr++) {
        const int i = o0 + rr;
        unsigned long long wd[5];
#pragma unroll
        for (int a = 0; a < 5; a++) wd[a] = sW2d[rr * 5 + a];

        unsigned long long vlo = 0ull, vhi = 0ull;
#pragma unroll
        for (int a = 0; a < 5; a++) {
            vlo = ffma2(wd[a], h[a].x, vlo);
            vhi = ffma2(wd[a], h[a].y, vhi);
        }
        const float2 flo = unpack2(vlo);
        const float2 fhi = unpack2(vhi);
        float4 v;
        v.x = flo.x; v.y = flo.y; v.z = fhi.x; v.w = fhi.y;

        const int d = i - jo;
        if ((unsigned)d < 4u) {
            if (d == 0) v.x += REPS;
            else if (d == 1) v.y += REPS;
            else if (d == 2) v.z += REPS;
            else v.w += REPS;
        }
        *reinterpret_cast<float4*>(out + (size_t)i * 2048 + jo) = v;
    }
}

// ---------------------------------------------------------------------------
extern "C" void kernel_launch(void* const* d_in, const int* in_sizes, int n_in,
                              void* d_out, int out_size) {
    const float* X  = (const float*)d_in[0];   // (1, 4096, 4096) f32
    const float* W1 = (const float*)d_in[1];   // (4096, 5) f32
    const float* W2 = (const float*)d_in[2];   // (5, 2048) f32
    float* out = (float*)d_out;                // (2048, 2048) f32

    k_proj<<<dim3(4, GYP), 256>>>(X, W1, W2);

    // PDL launch of k_out: overlap its launch/prologue with k_proj's tail.
    cudaLaunchConfig_t cfg = {};
    cfg.gridDim  = dim3(2, 296);
    cfg.blockDim = dim3(256, 1, 1);
    cfg.dynamicSmemBytes = 0;
    cfg.stream = (cudaStream_t)0;   // legacy default stream (capture target)
    cudaLaunchAttribute attr[1];
    attr[0].id = cudaLaunchAttributeProgrammaticStreamSerialization;
    attr[0].val.programmaticStreamSerializationAllowed = 1;
    cfg.attrs = attr;
    cfg.numAttrs = 1;
    cudaLaunchKernelEx(&cfg, k_out, W2, (float*)d_out);
}

// round 13
// speedup vs baseline: 1.2284x; 1.0031x over previous
#include <cuda_runtime.h>

#define REPS 1e-4f
#define GYP 148
#define NBLK_PROJ (4 * GYP)

// Scratch (no allocations allowed). Zero-init at load; last k_proj block
// resets g_M/g_cnt after consuming, so graph replays see clean state.
__device__ float    g_M[25 * 32];  // each accumulator on its own 128B line
__device__ unsigned g_cnt;
__device__ float    g_H[5 * 2048]; // H = A5 @ W2, produced by last proj block

// ---- packed f32x2 helpers (k_out only) -------------------------------------
__device__ __forceinline__ unsigned long long ffma2(unsigned long long a,
                                                    unsigned long long b,
                                                    unsigned long long c) {
    unsigned long long d;
    asm("fma.rn.f32x2 %0, %1, %2, %3;" : "=l"(d) : "l"(a), "l"(b), "l"(c));
    return d;
}
__device__ __forceinline__ float2 unpack2(unsigned long long v) {
    float2 r;
    asm("mov.b64 {%0, %1}, %2;" : "=f"(r.x), "=f"(r.y) : "l"(v));
    return r;
}
__device__ __forceinline__ unsigned long long pack_dup(float v) {
    unsigned long long d;
    asm("mov.b64 %0, {%1, %1};" : "=l"(d) : "f"(v));
    return d;
}
__device__ __forceinline__ float fsqrt_fast(float x) {
    return x * __frsqrt_rn(x);
}

// ---------------------------------------------------------------------------
// K1: R4 body with PADDED W1 STAGE (8 floats/row, 16B-aligned):
//   inner row = 1 LDS.128 (w0-3) + 1 LDS.32 (w4) + 1 LDG.128 + 20 FFMA
//   -> 3 LSU ops per 16B instead of 6 (the W1 scalar-LDS storm was the
//      suspected MIO/LSU-slot binder).
// Grid (4,148), 4 blocks/SM, contiguous row bands.
// Last block: thread 0 runs fast-math 5x5 Jacobi; 256 threads emit H=A5@W2.
// ---------------------------------------------------------------------------
__global__ __launch_bounds__(256, 4) void k_proj(const float* __restrict__ X,
                                                 const float* __restrict__ W1,
                                                 const float* __restrict__ W2) {
    const int tid = threadIdx.x;
    const int j0  = blockIdx.x * 1024 + tid * 4;
    const int r0  = (blockIdx.y * 4096) / GYP;
    const int r1  = ((blockIdx.y + 1) * 4096) / GYP;
    const int R   = r1 - r0;                      // 27 or 28

    __shared__ __align__(16) float sW1p[28 * 8];  // padded: 8 floats/row
    __shared__ float sM[8][25];
    __shared__ float sA5[25];
    __shared__ bool  sLast;
    if (tid < R * 5) {
        const int rr = tid / 5, a = tid % 5;
        sW1p[rr * 8 + a] = W1[(r0 + rr) * 5 + a];
    }
    __syncthreads();

    float tacc[4][5];
#pragma unroll
    for (int cc = 0; cc < 4; cc++)
#pragma unroll
        for (int a = 0; a < 5; a++) tacc[cc][a] = 0.f;

    const float* Xb = X + (size_t)r0 * 4096 + j0;
    int r = 0;
    for (; r + 4 <= R; r += 4) {
        const float4 x0 = *reinterpret_cast<const float4*>(Xb + (size_t)(r + 0) * 4096);
        const float4 x1 = *reinterpret_cast<const float4*>(Xb + (size_t)(r + 1) * 4096);
        const float4 x2 = *reinterpret_cast<const float4*>(Xb + (size_t)(r + 2) * 4096);
        const float4 x3 = *reinterpret_cast<const float4*>(Xb + (size_t)(r + 3) * 4096);
        const float4 xs[4] = {x0, x1, x2, x3};
#pragma unroll
        for (int k = 0; k < 4; k++) {
            const float xv[4] = {xs[k].x, xs[k].y, xs[k].z, xs[k].w};
            const float4 wq = *reinterpret_cast<const float4*>(&sW1p[(r + k) * 8]);
            const float w4  = sW1p[(r + k) * 8 + 4];
            const float w[5] = {wq.x, wq.y, wq.z, wq.w, w4};
#pragma unroll
            for (int cc = 0; cc < 4; cc++)
#pragma unroll
                for (int a = 0; a < 5; a++) tacc[cc][a] += xv[cc] * w[a];
        }
    }
    for (; r < R; r++) {
        const float4 x = *reinterpret_cast<const float4*>(Xb + (size_t)r * 4096);
        const float xv[4] = {x.x, x.y, x.z, x.w};
        const float4 wq = *reinterpret_cast<const float4*>(&sW1p[r * 8]);
        const float w4  = sW1p[r * 8 + 4];
        const float w[5] = {wq.x, wq.y, wq.z, wq.w, w4};
#pragma unroll
        for (int cc = 0; cc < 4; cc++)
#pragma unroll
            for (int a = 0; a < 5; a++) tacc[cc][a] += xv[cc] * w[a];
    }

    // Fold with W1[j,b] once per thread
    float mp[5][5];
#pragma unroll
    for (int a = 0; a < 5; a++)
#pragma unroll
        for (int b = 0; b < 5; b++) mp[a][b] = 0.f;
#pragma unroll
    for (int cc = 0; cc < 4; cc++) {
        float w1j[5];
#pragma unroll
        for (int b = 0; b < 5; b++) w1j[b] = __ldg(W1 + (j0 + cc) * 5 + b);
#pragma unroll
        for (int a = 0; a < 5; a++)
#pragma unroll
            for (int b = 0; b < 5; b++) mp[a][b] += tacc[cc][a] * w1j[b];
    }

    // Block reduce 25 values -> 25 padded global atomics
    const int lane = tid & 31, warp = tid >> 5;
#pragma unroll
    for (int e = 0; e < 25; e++) {
        float v = mp[e / 5][e % 5];
#pragma unroll
        for (int o = 16; o > 0; o >>= 1) v += __shfl_down_sync(0xffffffffu, v, o);
        if (lane == 0) sM[warp][e] = v;
    }
    __syncthreads();
    if (tid < 25) {
        float v = 0.f;
#pragma unroll
        for (int wq2 = 0; wq2 < 8; wq2++) v += sM[wq2][tid];
        atomicAdd(&g_M[tid * 32], v);
    }
    if (tid == 0) {
        __threadfence();
        sLast = (atomicAdd(&g_cnt, 1u) == (unsigned)NBLK_PROJ - 1u);
    }
    __syncthreads();
    if (!sLast) return;

    // ---- Last block. Thread 0: B = M*M^T ; fast Jacobi ; A5 -> shared ----
    if (tid == 0) {
        float m[5][5], b[5][5], u[5][5];
#pragma unroll
        for (int a = 0; a < 5; a++)
#pragma unroll
            for (int c = 0; c < 5; c++) m[a][c] = __ldcg(&g_M[(a * 5 + c) * 32]);

        float tr = 0.f;
#pragma unroll
        for (int a = 0; a < 5; a++)
#pragma unroll
            for (int c = 0; c < 5; c++) {
                float s = 0.f;
#pragma unroll
                for (int k = 0; k < 5; k++) s += m[a][k] * m[c][k];
                b[a][c] = s;
                u[a][c] = (a == c) ? 1.f : 0.f;
                if (a == c) tr += s;
            }
        const float skip_tol = 1e-7f * tr;

#pragma unroll
        for (int sweep = 0; sweep < 5; sweep++) {
#pragma unroll
            for (int p = 0; p < 4; p++) {
#pragma unroll
                for (int q = p + 1; q < 5; q++) {
                    const float apq = b[p][q];
                    if (fabsf(apq) > skip_tol) {
                        const float tau = __fdividef(b[q][q] - b[p][p], 2.f * apq);
                        const float h   = fsqrt_fast(1.f + tau * tau);
                        const float t   = copysignf(__fdividef(1.f, fabsf(tau) + h), tau);
                        const float c   = __frsqrt_rn(1.f + t * t);
                        const float s   = t * c;
#pragma unroll
                        for (int k = 0; k < 5; k++) {
                            const float bkp = b[k][p], bkq = b[k][q];
                            b[k][p] = c * bkp - s * bkq;
                            b[k][q] = s * bkp + c * bkq;
                        }
#pragma unroll
                        for (int k = 0; k < 5; k++) {
                            const float bpk = b[p][k], bqk = b[q][k];
                            b[p][k] = c * bpk - s * bqk;
                            b[q][k] = s * bpk + c * bqk;
                            const float ukp = u[k][p], ukq = u[k][q];
                            u[k][p] = c * ukp - s * ukq;
                            u[k][q] = s * ukp + c * ukq;
                        }
                    }
                }
            }
        }

        float f[5];
#pragma unroll
        for (int d = 0; d < 5; d++) {
            const float lam = fmaxf(b[d][d], 0.f);
            f[d] = fmaxf(sqrtf(lam), REPS) - REPS;
        }
#pragma unroll
        for (int a = 0; a < 5; a++)
#pragma unroll
            for (int c = 0; c < 5; c++) {
                float s = 0.f;
#pragma unroll
                for (int d = 0; d < 5; d++) s += u[a][d] * f[d] * u[c][d];
                sA5[a * 5 + c] = s;
            }

        // Reset scratch for the next graph replay
#pragma unroll
        for (int e = 0; e < 25; e++) g_M[e * 32] = 0.f;
        g_cnt = 0u;
    }
    __syncthreads();

    // ---- All 256 threads: H[a][j] = sum_b A5[a][b] * W2[b][j] -> g_H ----
    float a5[5][5];
#pragma unroll
    for (int a = 0; a < 5; a++)
#pragma unroll
        for (int c = 0; c < 5; c++) a5[a][c] = sA5[a * 5 + c];
#pragma unroll
    for (int k = 0; k < 8; k++) {
        const int j = tid + 256 * k;
        float w2j[5];
#pragma unroll
        for (int b2 = 0; b2 < 5; b2++) w2j[b2] = __ldg(W2 + b2 * 2048 + j);
#pragma unroll
        for (int a = 0; a < 5; a++) {
            float s = 0.f;
#pragma unroll
            for (int b2 = 0; b2 < 5; b2++) s += a5[a][b2] * w2j[b2];
            g_H[a * 2048 + j] = s;
        }
    }
}

// ---------------------------------------------------------------------------
// K2 (R10 body — best measured, 6.7us): z = W2^T H + EPS*I. Plain launch.
// W2 band slice staged in smem as duplicated pairs ONCE; inner row loop is
// 5 LDS.64 + 10 fma.rn.f32x2 + STG.128 — zero LDG.
// ---------------------------------------------------------------------------
__global__ __launch_bounds__(256, 4) void k_out(const float* __restrict__ W2,
                                                float* __restrict__ out) {
    const int tid = threadIdx.x;
    const int jo  = blockIdx.x * 1024 + tid * 4;
    const int o0  = (blockIdx.y * 2048) / 296;
    const int o1  = ((blockIdx.y + 1) * 2048) / 296;
    const int RR  = o1 - o0;                      // 6 or 7

    __shared__ __align__(8) unsigned long long sW2d[8 * 5];  // (w,w) per row,a
    if (tid < RR * 5) {
        const int rr = tid / 5, a = tid % 5;
        sW2d[tid] = pack_dup(__ldg(W2 + a * 2048 + o0 + rr));
    }

    ulonglong2 h[5];
#pragma unroll
    for (int a = 0; a < 5; a++)
        h[a] = *reinterpret_cast<const ulonglong2*>(g_H + a * 2048 + jo);
    __syncthreads();

    for (int rr = 0; rr < RR; rr++) {
        const int i = o0 + rr;
        unsigned long long wd[5];
#pragma unroll
        for (int a = 0; a < 5; a++) wd[a] = sW2d[rr * 5 + a];

        unsigned long long vlo = 0ull, vhi = 0ull;
#pragma unroll
        for (int a = 0; a < 5; a++) {
            vlo = ffma2(wd[a], h[a].x, vlo);
            vhi = ffma2(wd[a], h[a].y, vhi);
        }
        const float2 flo = unpack2(vlo);
        const float2 fhi = unpack2(vhi);
        float4 v;
        v.x = flo.x; v.y = flo.y; v.z = fhi.x; v.w = fhi.y;

        const int d = i - jo;
        if ((unsigned)d < 4u) {
            if (d == 0) v.x += REPS;
            else if (d == 1) v.y += REPS;
            else if (d == 2) v.z += REPS;
            else v.w += REPS;
        }
        *reinterpret_cast<float4*>(out + (size_t)i * 2048 + jo) = v;
    }
}

// ---------------------------------------------------------------------------
extern "C" void kernel_launch(void* const* d_in, const int* in_sizes, int n_in,
                              void* d_out, int out_size) {
    const float* X  = (const float*)d_in[0];   // (1, 4096, 4096) f32
    const float* W1 = (const float*)d_in[1];   // (4096, 5) f32
    const float* W2 = (const float*)d_in[2];   // (5, 2048) f32
    float* out = (float*)d_out;                // (2048, 2048) f32

    k_proj<<<dim3(4, GYP), 256>>>(X, W1, W2);
    k_out <<<dim3(2, 296), 256>>>(W2, out);
}